// round 4
// baseline (speedup 1.0000x reference)
#include <cuda_runtime.h>
#include <cuda_bf16.h>
#include <math.h>
#include <stdint.h>

#define Bn 4
#define Cn 512
#define Ln 4096

// ---------------------------------------------------------------------------
// Scratch (static device globals; no allocation allowed)
// ---------------------------------------------------------------------------
__device__ float g_E[(size_t)Bn * Ln * Ln];                    // energy fp32 [b][i][j]
__device__ __nv_bfloat16 g_Qt_hi[(size_t)Bn * Ln * Cn];        // Q^T  [b][i][c]
__device__ __nv_bfloat16 g_Qt_lo[(size_t)Bn * Ln * Cn];
__device__ __nv_bfloat16 g_Kt_hi[(size_t)Bn * Ln * Cn];        // K^T  [b][j][c]
__device__ __nv_bfloat16 g_Kt_lo[(size_t)Bn * Ln * Cn];
__device__ __nv_bfloat16 g_V_hi[(size_t)Bn * Cn * Ln];         // V    [b][c][j]
__device__ __nv_bfloat16 g_V_lo[(size_t)Bn * Cn * Ln];
__device__ __nv_bfloat16 g_P_hi[(size_t)Bn * Ln * Ln];         // att  [b][i][j]
__device__ __nv_bfloat16 g_P_lo[(size_t)Bn * Ln * Ln];

// ---------------------------------------------------------------------------
// Base-ISA helpers (compute_103-safe: ldmatrix / mma.sync / cp.async)
// ---------------------------------------------------------------------------
__device__ __forceinline__ uint32_t smem_u32(const void* p) {
    uint32_t a;
    asm("{ .reg .u64 t; cvta.to.shared.u64 t, %1; cvt.u32.u64 %0, t; }" : "=r"(a) : "l"(p));
    return a;
}
__device__ __forceinline__ void ldsm_x4(uint32_t addr, uint32_t r[4]) {
    asm volatile("ldmatrix.sync.aligned.m8n8.x4.shared.b16 {%0,%1,%2,%3}, [%4];"
                 : "=r"(r[0]), "=r"(r[1]), "=r"(r[2]), "=r"(r[3]) : "r"(addr));
}
__device__ __forceinline__ void mma_bf16(float d[4], const uint32_t a[4], const uint32_t b[2]) {
    asm volatile("mma.sync.aligned.m16n8k16.row.col.f32.bf16.bf16.f32 "
                 "{%0,%1,%2,%3}, {%4,%5,%6,%7}, {%8,%9}, {%0,%1,%2,%3};"
                 : "+f"(d[0]), "+f"(d[1]), "+f"(d[2]), "+f"(d[3])
                 : "r"(a[0]), "r"(a[1]), "r"(a[2]), "r"(a[3]), "r"(b[0]), "r"(b[1]));
}
#define CP16(d, s) asm volatile("cp.async.cg.shared.global [%0], [%1], 16;" :: "r"(d), "l"(s))
#define CP_COMMIT() asm volatile("cp.async.commit_group;" ::: "memory")
#define CP_WAIT1()  asm volatile("cp.async.wait_group 1;" ::: "memory")
#define CP_WAIT0()  asm volatile("cp.async.wait_group 0;" ::: "memory")

__device__ __forceinline__ void split_bf16(float x, __nv_bfloat16& h, __nv_bfloat16& l) {
    h = __float2bfloat16(x);
    l = __float2bfloat16(x - __bfloat162float(h));
}

// ---------------------------------------------------------------------------
// smem geometry: 4 tiles (Ah, Al, Bh, Bl), each 128 rows x 32 bf16, row
// stride padded to 80 B (conflict-free ldmatrix). Double buffered.
// ---------------------------------------------------------------------------
#define ROWB 80
#define TILE_B (128 * ROWB)        // 10240
#define OFF_AH 0
#define OFF_AL (1 * TILE_B)
#define OFF_BH (2 * TILE_B)
#define OFF_BL (3 * TILE_B)
#define BUF_B  (4 * TILE_B)        // 40960
#define LM_OFF (2 * BUF_B)         // 81920
#define SMEM_BYTES (2 * BUF_B + 512)

// ---------------------------------------------------------------------------
// bf16x3 tensor-core GEMM, 128x128 tile, BK=32, 256 threads, double buffer.
// FIRST: E[i][j] = (Qt[i][:] . Kt[j][:]) * scale + logmask[j]    (K = 512)
// !FIRST: out[c][i] = V[c][:] . P[i][:]                          (K = 4096)
// ---------------------------------------------------------------------------
template <bool FIRST>
__global__ __launch_bounds__(256) void mma_gemm_kernel(float* __restrict__ Dout,
                                                       const float* __restrict__ mask)
{
    constexpr int KTOT = FIRST ? Cn : Ln;
    constexpr int LD   = FIRST ? Cn : Ln;       // K-stride of A and B rows
    constexpr int NIT  = KTOT / 32;

    extern __shared__ char smem[];
    const uint32_t sbase = smem_u32(smem);
    const int tid = threadIdx.x;
    const int b = blockIdx.z;
    // FIRST: x = n-tiles (j), y = m-tiles (i).  !FIRST: x = m-tiles (c, 4 of
    // them), y = n-tiles (i) — CTAs sharing a B (P) tile are launch-adjacent.
    const int n0 = (FIRST ? blockIdx.x : blockIdx.y) * 128;
    const int m0 = (FIRST ? blockIdx.y : blockIdx.x) * 128;

    const __nv_bfloat16* Ah = (FIRST ? g_Qt_hi : g_V_hi) + ((size_t)b * (FIRST ? Ln : Cn) + m0) * LD;
    const __nv_bfloat16* Al = (FIRST ? g_Qt_lo : g_V_lo) + ((size_t)b * (FIRST ? Ln : Cn) + m0) * LD;
    const __nv_bfloat16* Bh = (FIRST ? g_Kt_hi : g_P_hi) + ((size_t)b * Ln + n0) * LD;
    const __nv_bfloat16* Bl = (FIRST ? g_Kt_lo : g_P_lo) + ((size_t)b * Ln + n0) * LD;
    float* D = (FIRST ? g_E : Dout) + (size_t)b * (FIRST ? Ln : Cn) * Ln;

    float* lmp = (float*)(smem + LM_OFF);
    if (FIRST && tid < 128)
        lmp[tid] = logf(mask[(size_t)b * Ln + n0 + tid] + 1e-6f);

    const int lane = tid & 31, wid = tid >> 5;
    const int wm = wid & 3, wn = wid >> 2;         // warp tile: 32 (m) x 64 (n)
    const int quad = lane >> 3, qj = lane & 7;
    const int a_row = (quad & 1) * 8 + qj;         // within m16
    const int a_kb  = (quad >> 1) * 16;            // byte offset within k16 row
    const int b_row = (quad >> 1) * 8 + qj;        // within n16
    const int b_kb  = (quad & 1) * 16;

    float acc[2][8][4];
#pragma unroll
    for (int fm = 0; fm < 2; fm++)
#pragma unroll
        for (int fn = 0; fn < 8; fn++)
#pragma unroll
            for (int e = 0; e < 4; e++) acc[fm][fn][e] = 0.0f;

    // ---- loader: one BK=32 slab into buffer `buf` --------------------------
    auto load_slab = [&](int buf, int it) {
        const uint32_t bb = sbase + buf * BUF_B;
        const int k0 = it * 32;
#pragma unroll
        for (int t = 0; t < 2; t++) {
            int f = t * 256 + tid;                 // 0..511
            int row = f >> 2, ch = f & 3;          // 128 rows x 4 x 16B
            uint32_t doff = row * ROWB + ch * 16;
            size_t soff = (size_t)row * LD + k0 + ch * 8;
            CP16(bb + OFF_AH + doff, Ah + soff);
            CP16(bb + OFF_AL + doff, Al + soff);
            CP16(bb + OFF_BH + doff, Bh + soff);
            CP16(bb + OFF_BL + doff, Bl + soff);
        }
        CP_COMMIT();
    };

    load_slab(0, 0);

    for (int it = 0; it < NIT; it++) {
        const int buf = it & 1;
        if (it + 1 < NIT) { load_slab(buf ^ 1, it + 1); CP_WAIT1(); }
        else              { CP_WAIT0(); }
        __syncthreads();

        const uint32_t bb = sbase + buf * BUF_B;
#pragma unroll
        for (int ks = 0; ks < 2; ks++) {
            uint32_t ah[2][4], al[2][4];
#pragma unroll
            for (int fm = 0; fm < 2; fm++) {
                uint32_t r = (wm * 32 + fm * 16 + a_row) * ROWB + ks * 32 + a_kb;
                ldsm_x4(bb + OFF_AH + r, ah[fm]);
                ldsm_x4(bb + OFF_AL + r, al[fm]);
            }
#pragma unroll
            for (int h = 0; h < 2; h++) {
                uint32_t bh[4][2], bl[4][2];
#pragma unroll
                for (int g = 0; g < 2; g++) {
                    uint32_t r = (wn * 64 + h * 32 + g * 16 + b_row) * ROWB + ks * 32 + b_kb;
                    uint32_t t4[4];
                    ldsm_x4(bb + OFF_BH + r, t4);
                    bh[g * 2][0] = t4[0]; bh[g * 2][1] = t4[1];
                    bh[g * 2 + 1][0] = t4[2]; bh[g * 2 + 1][1] = t4[3];
                    ldsm_x4(bb + OFF_BL + r, t4);
                    bl[g * 2][0] = t4[0]; bl[g * 2][1] = t4[1];
                    bl[g * 2 + 1][0] = t4[2]; bl[g * 2 + 1][1] = t4[3];
                }
                // Three term passes (hh, hl, lh): 8 independent MMAs between
                // successive writes to any given accumulator -> no RAW bubbles.
#pragma unroll
                for (int fm = 0; fm < 2; fm++)
#pragma unroll
                    for (int fl = 0; fl < 4; fl++)
                        mma_bf16(acc[fm][h * 4 + fl], ah[fm], bh[fl]);
#pragma unroll
                for (int fm = 0; fm < 2; fm++)
#pragma unroll
                    for (int fl = 0; fl < 4; fl++)
                        mma_bf16(acc[fm][h * 4 + fl], ah[fm], bl[fl]);
#pragma unroll
                for (int fm = 0; fm < 2; fm++)
#pragma unroll
                    for (int fl = 0; fl < 4; fl++)
                        mma_bf16(acc[fm][h * 4 + fl], al[fm], bh[fl]);
            }
        }
        __syncthreads();
    }

    // ---- epilogue -----------------------------------------------------------
    const float scale = 0.04419417382415922f;      // 1/sqrt(512)
#pragma unroll
    for (int fm = 0; fm < 2; fm++)
#pragma unroll
        for (int fn = 0; fn < 8; fn++) {
            int r0 = m0 + wm * 32 + fm * 16 + (lane >> 2);
            int cl = wn * 64 + fn * 8 + (lane & 3) * 2;   // local col
            float v0 = acc[fm][fn][0], v1 = acc[fm][fn][1];
            float v2 = acc[fm][fn][2], v3 = acc[fm][fn][3];
            if (FIRST) {
                v0 = v0 * scale + lmp[cl];     v1 = v1 * scale + lmp[cl + 1];
                v2 = v2 * scale + lmp[cl];     v3 = v3 * scale + lmp[cl + 1];
            }
            *(float2*)&D[(size_t)r0 * Ln + n0 + cl]       = make_float2(v0, v1);
            *(float2*)&D[(size_t)(r0 + 8) * Ln + n0 + cl] = make_float2(v2, v3);
        }
}

// ---------------------------------------------------------------------------
// Convert + transpose Q,K: [b][C][L] fp32 -> [b][L][C] bf16 hi/lo
// ---------------------------------------------------------------------------
template <bool ISQ>
__global__ void convT_kernel(const float* __restrict__ X)
{
    __shared__ float tile[32][33];
    const int b = blockIdx.z, l0 = blockIdx.x * 32, c0 = blockIdx.y * 32;
    const int tx = threadIdx.x, ty = threadIdx.y;
#pragma unroll
    for (int r = 0; r < 32; r += 8)
        tile[ty + r][tx] = X[((size_t)b * Cn + c0 + ty + r) * Ln + l0 + tx];
    __syncthreads();
    __nv_bfloat16* Hi = ISQ ? g_Qt_hi : g_Kt_hi;
    __nv_bfloat16* Lo = ISQ ? g_Qt_lo : g_Kt_lo;
#pragma unroll
    for (int r = 0; r < 32; r += 8) {
        float v = tile[tx][ty + r];
        __nv_bfloat16 h, l; split_bf16(v, h, l);
        size_t idx = ((size_t)b * Ln + l0 + ty + r) * Cn + c0 + tx;
        Hi[idx] = h; Lo[idx] = l;
    }
}

// Convert V elementwise: fp32 -> bf16 hi/lo (same [b][C][L] layout)
__global__ void convV_kernel(const float* __restrict__ V)
{
    size_t idx = ((size_t)blockIdx.x * 256 + threadIdx.x) * 2;
    float2 v = *(const float2*)(V + idx);
    __nv_bfloat16 h0, l0, h1, l1;
    split_bf16(v.x, h0, l0); split_bf16(v.y, h1, l1);
    *(__nv_bfloat162*)(g_V_hi + idx) = __nv_bfloat162(h0, h1);
    *(__nv_bfloat162*)(g_V_lo + idx) = __nv_bfloat162(l0, l1);
}

// ---------------------------------------------------------------------------
// Row softmax over j + mask multiply; emits att as bf16 hi/lo [b][i][j]
// ---------------------------------------------------------------------------
__global__ __launch_bounds__(256) void softmax_mask_kernel(const float* __restrict__ mask)
{
    const int b = blockIdx.y, i = blockIdx.x;
    const size_t rowbase = ((size_t)b * Ln + i) * Ln;
    const float* row = g_E + rowbase;
    const float* mrow = mask + (size_t)b * Ln;
    const int tid = threadIdx.x;
    __shared__ float red[8];

    float v[16];
    float mx = -3.0e38f;
#pragma unroll
    for (int t = 0; t < 16; t++) { v[t] = row[t * 256 + tid]; mx = fmaxf(mx, v[t]); }
#pragma unroll
    for (int o = 16; o > 0; o >>= 1) mx = fmaxf(mx, __shfl_xor_sync(0xffffffffu, mx, o));
    if ((tid & 31) == 0) red[tid >> 5] = mx;
    __syncthreads();
    if (tid < 32) {
        float x = (tid < 8) ? red[tid] : -3.0e38f;
#pragma unroll
        for (int o = 4; o > 0; o >>= 1) x = fmaxf(x, __shfl_xor_sync(0xffffffffu, x, o));
        if (tid == 0) red[0] = x;
    }
    __syncthreads();
    mx = red[0];
    __syncthreads();

    float s = 0.0f;
#pragma unroll
    for (int t = 0; t < 16; t++) { v[t] = expf(v[t] - mx); s += v[t]; }
#pragma unroll
    for (int o = 16; o > 0; o >>= 1) s += __shfl_xor_sync(0xffffffffu, s, o);
    if ((tid & 31) == 0) red[tid >> 5] = s;
    __syncthreads();
    if (tid < 32) {
        float x = (tid < 8) ? red[tid] : 0.0f;
#pragma unroll
        for (int o = 4; o > 0; o >>= 1) x += __shfl_xor_sync(0xffffffffu, x, o);
        if (tid == 0) red[0] = x;
    }
    __syncthreads();
    const float inv = 1.0f / red[0];

#pragma unroll
    for (int t = 0; t < 16; t++) {
        const int j = t * 256 + tid;
        float val = v[t] * inv * mrow[j];
        __nv_bfloat16 h, l; split_bf16(val, h, l);
        g_P_hi[rowbase + j] = h;
        g_P_lo[rowbase + j] = l;
    }
}

// ---------------------------------------------------------------------------
// attT[b][j][i] = att[b][i][j]   (output-only transpose, hi+lo reconstruct)
// ---------------------------------------------------------------------------
__global__ void transP_kernel(float* __restrict__ AT)
{
    __shared__ float tile[32][33];
    const int b = blockIdx.z, j0 = blockIdx.x * 32, i0 = blockIdx.y * 32;
    const int tx = threadIdx.x, ty = threadIdx.y;
    float* Tb = AT + (size_t)b * Ln * Ln;
#pragma unroll
    for (int r = 0; r < 32; r += 8) {
        size_t idx = ((size_t)b * Ln + i0 + ty + r) * Ln + j0 + tx;
        tile[ty + r][tx] = __bfloat162float(g_P_hi[idx]) + __bfloat162float(g_P_lo[idx]);
    }
    __syncthreads();
#pragma unroll
    for (int r = 0; r < 32; r += 8)
        Tb[(size_t)(j0 + ty + r) * Ln + i0 + tx] = tile[tx][ty + r];
}

// ---------------------------------------------------------------------------
extern "C" void kernel_launch(void* const* d_in, const int* in_sizes, int n_in,
                              void* d_out, int out_size)
{
    const float* Q    = (const float*)d_in[0];
    const float* Kt   = (const float*)d_in[1];
    const float* V    = (const float*)d_in[2];
    const float* mask = (const float*)d_in[3];

    float* out  = (float*)d_out;                   // (B, C, L)
    float* attT = out + (size_t)Bn * Cn * Ln;      // (B, L, L)

    cudaFuncSetAttribute(mma_gemm_kernel<true>,
                         cudaFuncAttributeMaxDynamicSharedMemorySize, SMEM_BYTES);
    cudaFuncSetAttribute(mma_gemm_kernel<false>,
                         cudaFuncAttributeMaxDynamicSharedMemorySize, SMEM_BYTES);

    convT_kernel<true><<<dim3(Ln / 32, Cn / 32, Bn), dim3(32, 8)>>>(Q);
    convT_kernel<false><<<dim3(Ln / 32, Cn / 32, Bn), dim3(32, 8)>>>(Kt);
    convV_kernel<<<(int)(((size_t)Bn * Cn * Ln) / 512), 256>>>(V);

    mma_gemm_kernel<true><<<dim3(Ln / 128, Ln / 128, Bn), 256, SMEM_BYTES>>>(nullptr, mask);
    softmax_mask_kernel<<<dim3(Ln, Bn), 256>>>(mask);
    mma_gemm_kernel<false><<<dim3(Cn / 128, Ln / 128, Bn), 256, SMEM_BYTES>>>(out, nullptr);
    transP_kernel<<<dim3(Ln / 32, Ln / 32, Bn), dim3(32, 8)>>>(attT);
}